// round 9
// baseline (speedup 1.0000x reference)
#include <cuda_runtime.h>
#include <stdint.h>
#include <math.h>

#define Bb 64
#define Nn 3
#define Tt 4096
#define Dd 64
#define Hh 128
#define ROWS ((size_t)Bb * Nn * Tt)   // 786432

typedef unsigned long long u64;

// -------- packed f32x2 helpers (Blackwell fma.rn.f32x2) --------
__device__ __forceinline__ u64 pk(float lo, float hi) {
    u64 r; asm("mov.b64 %0,{%1,%2};" : "=l"(r) : "f"(lo), "f"(hi)); return r;
}
__device__ __forceinline__ void upk(u64 v, float& lo, float& hi) {
    asm("mov.b64 {%0,%1},%2;" : "=f"(lo), "=f"(hi) : "l"(v));
}
__device__ __forceinline__ u64 f2fma(u64 a, u64 b, u64 c) {
    u64 d; asm("fma.rn.f32x2 %0,%1,%2,%3;" : "=l"(d) : "l"(a), "l"(b), "l"(c)); return d;
}
__device__ __forceinline__ float fex2(float x) {
    float r; asm("ex2.approx.f32 %0,%1;" : "=f"(r) : "f"(x)); return r;
}
__device__ __forceinline__ float frcp(float x) {
    float r; asm("rcp.approx.f32 %0,%1;" : "=f"(r) : "f"(x)); return r;
}
#define LOG2E 1.4426950408889634f
__device__ __forceinline__ float fsig(float x) { return frcp(1.f + fex2(-x * LOG2E)); }
__device__ __forceinline__ float ftanh_f(float x) { return 1.f - 2.f * frcp(1.f + fex2(x * (2.f * LOG2E))); }

// -------- scratch (static device globals; no runtime allocation) --------
__device__ float g_h  [(size_t)Bb * Nn * Tt * Hh];
__device__ float g_hsp[(size_t)Bb * Nn * Tt * Hh];
__device__ float g_gx [(size_t)Bb * Nn * Tt * 3 * Hh];

// ============================================================
// Kernel A: h = x @ gat_W + gat_b      (786432 x 64) @ (64 x 128)  [f32x2]
// ============================================================
__global__ __launch_bounds__(128) void gat_kernel(const float* __restrict__ x,
                                                  const float* __restrict__ W,
                                                  const float* __restrict__ bias)
{
    __shared__ __align__(16) float xs[16][64];
    const int c = threadIdx.x;
    const size_t r0 = (size_t)blockIdx.x * 16;

    {
        const float4* src = (const float4*)(x + r0 * Dd);
        float4* dst = (float4*)xs;
        dst[c]       = src[c];
        dst[c + 128] = src[c + 128];
    }
    u64 w2[32];
#pragma unroll
    for (int i = 0; i < 32; i++)
        w2[i] = pk(W[(2 * i) * Hh + c], W[(2 * i + 1) * Hh + c]);
    const float bv = bias[c];
    __syncthreads();

#pragma unroll 4
    for (int r = 0; r < 16; r++) {
        const ulonglong2* xr = (const ulonglong2*)xs[r];
        u64 a0 = 0ull, a1 = 0ull;
#pragma unroll
        for (int i = 0; i < 16; i++) {
            ulonglong2 xv = xr[i];
            a0 = f2fma(xv.x, w2[2 * i],     a0);
            a1 = f2fma(xv.y, w2[2 * i + 1], a1);
        }
        float l0, h0, l1, h1; upk(a0, l0, h0); upk(a1, l1, h1);
        g_h[(r0 + r) * Hh + c] = (l0 + h0) + (l1 + h1) + bv;
    }
}

// ============================================================
// Kernel B: attention + softmax + ELU + spatial LayerNorm
// Warp-per-timestep: lane holds 4 H-columns; shuffle-only reductions.
// ============================================================
__global__ __launch_bounds__(256) void attn_kernel(const float* __restrict__ a_src,
                                                   const float* __restrict__ a_dst,
                                                   const float* __restrict__ abias,
                                                   const float* __restrict__ sng,
                                                   const float* __restrict__ snb)
{
    const int lane = threadIdx.x & 31;
    const int wix  = blockIdx.x * 8 + (threadIdx.x >> 5);  // global warp id
    const int b = wix >> 12;            // / 4096
    const int t = wix & 4095;

    const float4 as4 = ((const float4*)a_src)[lane];
    const float4 ad4 = ((const float4*)a_dst)[lane];
    const float4 gw4 = ((const float4*)sng)[lane];
    const float4 gb4 = ((const float4*)snb)[lane];

    float bi[9];
#pragma unroll
    for (int q = 0; q < 9; q++) bi[q] = __ldg(abias + q);

    float4 hv[3];
#pragma unroll
    for (int j = 0; j < 3; j++)
        hv[j] = *(const float4*)(g_h + (((size_t)b * Nn + j) * Tt + t) * Hh + lane * 4);

    // 6 dot products over H via shuffle butterfly
    float v[6];
#pragma unroll
    for (int j = 0; j < 3; j++) {
        v[j]     = hv[j].x * as4.x + hv[j].y * as4.y + hv[j].z * as4.z + hv[j].w * as4.w;
        v[3 + j] = hv[j].x * ad4.x + hv[j].y * ad4.y + hv[j].z * ad4.z + hv[j].w * ad4.w;
    }
#pragma unroll
    for (int off = 16; off; off >>= 1) {
#pragma unroll
        for (int q = 0; q < 6; q++)
            v[q] += __shfl_xor_sync(0xffffffffu, v[q], off);
    }

    // per-destination softmax over sources + combine + ELU (float4 per lane)
    float4 o[3];
#pragma unroll
    for (int i = 0; i < 3; i++) {
        float sc[3];
#pragma unroll
        for (int j = 0; j < 3; j++) {
            float s = v[i] + v[3 + j];
            s = s > 0.f ? s : 0.2f * s;
            sc[j] = s + bi[i * 3 + j];
        }
        float mx = fmaxf(sc[0], fmaxf(sc[1], sc[2]));
        float e0 = __expf(sc[0] - mx), e1 = __expf(sc[1] - mx), e2 = __expf(sc[2] - mx);
        float inv = frcp(e0 + e1 + e2);
        e0 *= inv; e1 *= inv; e2 *= inv;
        float4 ov;
        ov.x = e0 * hv[0].x + e1 * hv[1].x + e2 * hv[2].x;
        ov.y = e0 * hv[0].y + e1 * hv[1].y + e2 * hv[2].y;
        ov.z = e0 * hv[0].z + e1 * hv[1].z + e2 * hv[2].z;
        ov.w = e0 * hv[0].w + e1 * hv[1].w + e2 * hv[2].w;
        ov.x = ov.x > 0.f ? ov.x : (__expf(ov.x) - 1.f);
        ov.y = ov.y > 0.f ? ov.y : (__expf(ov.y) - 1.f);
        ov.z = ov.z > 0.f ? ov.z : (__expf(ov.z) - 1.f);
        ov.w = ov.w > 0.f ? ov.w : (__expf(ov.w) - 1.f);
        o[i] = ov;
    }

    // LayerNorm stats per destination node i
    float st[6];
#pragma unroll
    for (int i = 0; i < 3; i++) {
        st[2*i]   = o[i].x + o[i].y + o[i].z + o[i].w;
        st[2*i+1] = o[i].x*o[i].x + o[i].y*o[i].y + o[i].z*o[i].z + o[i].w*o[i].w;
    }
#pragma unroll
    for (int off = 16; off; off >>= 1) {
#pragma unroll
        for (int q = 0; q < 6; q++)
            st[q] += __shfl_xor_sync(0xffffffffu, st[q], off);
    }
#pragma unroll
    for (int i = 0; i < 3; i++) {
        float mean = st[2*i] * (1.f / Hh);
        float var  = st[2*i+1] * (1.f / Hh) - mean * mean;
        float rstd = rsqrtf(var + 1e-5f);
        float4 r;
        r.x = (o[i].x - mean) * rstd * gw4.x + gb4.x;
        r.y = (o[i].y - mean) * rstd * gw4.y + gb4.y;
        r.z = (o[i].z - mean) * rstd * gw4.z + gb4.z;
        r.w = (o[i].w - mean) * rstd * gw4.w + gb4.w;
        *(float4*)(g_hsp + (((size_t)b * Nn + i) * Tt + t) * Hh + lane * 4) = r;
    }
}

// ============================================================
// Kernel C: gx = h_sp @ W_ih^T + b_ih   [f32x2]  (unchanged, proven)
// ============================================================
__global__ __launch_bounds__(256) void gx_kernel(const float* __restrict__ Wih,
                                                 const float* __restrict__ bih)
{
    __shared__ __align__(16) float hs[32][128];
    __shared__ float ws[128][33];

    const int tid = threadIdx.x;
    const int gg  = tid & 127;
    const int rh  = tid >> 7;
    const int g0  = blockIdx.y * 128;
    const size_t r0 = (size_t)blockIdx.x * 32;

    {
        const float4* src = (const float4*)(g_hsp + r0 * Hh);
        float4* dst = (float4*)hs;
#pragma unroll
        for (int i = 0; i < 4; i++) dst[tid + 256 * i] = src[tid + 256 * i];
    }

    u64 acc[16];
#pragma unroll
    for (int i = 0; i < 16; i++) acc[i] = 0ull;

    for (int p = 0; p < 4; p++) {
        if (p) __syncthreads();
#pragma unroll
        for (int i = 0; i < 16; i++) {
            int idx = tid + 256 * i;
            int row = idx >> 5, k = idx & 31;
            ws[row][k] = Wih[(size_t)(g0 + row) * Hh + p * 32 + k];
        }
        __syncthreads();

        u64 w2[16];
#pragma unroll
        for (int i = 0; i < 16; i++)
            w2[i] = pk(ws[gg][2 * i], ws[gg][2 * i + 1]);

#pragma unroll
        for (int r = 0; r < 16; r++) {
            const ulonglong2* xr = (const ulonglong2*)(hs[rh * 16 + r] + p * 32);
#pragma unroll
            for (int i = 0; i < 8; i++) {
                ulonglong2 xv = xr[i];
                acc[r] = f2fma(xv.x, w2[2 * i],     acc[r]);
                acc[r] = f2fma(xv.y, w2[2 * i + 1], acc[r]);
            }
        }
    }

    const float bv = bih[g0 + gg];
#pragma unroll
    for (int r = 0; r < 16; r++) {
        size_t row = r0 + rh * 16 + r;
        float lo, hi; upk(acc[r], lo, hi);
        g_gx[row * 384 + g0 + gg] = lo + hi + bv;
    }
}

// ============================================================
// Kernel D: GRU, sequence-interleaved pipeline.
// 96 blocks x 384 threads; 2 sequences per block, half-step offset.
// Phase 0: matvec(A) by all threads || gates(B) by threads<128.
// Phase 1: matvec(B) || gates(A). Gate work hides in FFMA2 issue gaps.
// Thread u holds full W_hh row u (64 u64 regs).
// ============================================================
__global__ __launch_bounds__(384, 1) void gru_kernel(const float* __restrict__ Whh,
                                                     const float* __restrict__ bhh,
                                                     float* __restrict__ out)
{
    const int u = threadIdx.x;                  // row 0..383
    const int sA = blockIdx.x * 2;

    __shared__ __align__(16) float hA[128], hB[128];
    __shared__ float pxA[384], pxB[384];

    // full row of W_hh in registers (128 floats = 64 u64)
    u64 w[64];
    {
        const u64* wr = (const u64*)(Whh + (size_t)u * Hh);
#pragma unroll
        for (int i = 0; i < 64; i++) w[i] = wr[i];
    }
    const float bh = bhh[u];

    if (u < 128) { hA[u] = 0.f; hB[u] = 0.f; }
    pxB[u] = bh;                                // matvec(h=0) + bias

    const float* gxA = g_gx + (size_t)sA * Tt * 384;
    const float* gxB = gxA + (size_t)Tt * 384;
    float* opA = out + (size_t)sA * Tt * Hh;
    float* opB = opA + (size_t)Tt * Hh;

    // gate-thread prefetch registers (step 0)
    float frA = 0.f, fzA = 0.f, fnA = 0.f, frB = 0.f, fzB = 0.f, fnB = 0.f;
    if (u < 128) {
        frA = __ldg(gxA + u);       fzA = __ldg(gxA + u + 128); fnA = __ldg(gxA + u + 256);
        frB = __ldg(gxB + u);       fzB = __ldg(gxB + u + 128); fnB = __ldg(gxB + u + 256);
    }
    __syncthreads();

    for (int t = 0; t < Tt; t++) {
        const int tn = (t + 1 < Tt) ? t + 1 : t;

        // ---- Phase 0: matvec A (reads hA at t-1) + gates B (pxB -> hB at t) ----
        {
            const ulonglong2* h2 = (const ulonglong2*)hA;
            u64 a0 = 0ull, a1 = 0ull;
#pragma unroll
            for (int i = 0; i < 32; i++) {
                ulonglong2 hv = h2[i];
                a0 = f2fma(w[2 * i],     hv.x, a0);
                a1 = f2fma(w[2 * i + 1], hv.y, a1);
            }
            float l0, h0, l1, h1; upk(a0, l0, h0); upk(a1, l1, h1);
            pxA[u] = (l0 + h0) + (l1 + h1) + bh;

            if (u < 128) {
                const float r = fsig(frB + pxB[u]);
                const float z = fsig(fzB + pxB[u + 128]);
                const float n = ftanh_f(fnB + r * pxB[u + 256]);
                const float hnew = (1.f - z) * n + z * hB[u];
                hB[u] = hnew;
                opB[(size_t)t * Hh + u] = hnew;
                const float* nx = gxB + (size_t)tn * 384;
                frB = __ldg(nx + u); fzB = __ldg(nx + u + 128); fnB = __ldg(nx + u + 256);
            }
        }
        __syncthreads();

        // ---- Phase 1: matvec B (reads hB at t) + gates A (pxA -> hA at t) ----
        {
            const ulonglong2* h2 = (const ulonglong2*)hB;
            u64 a0 = 0ull, a1 = 0ull;
#pragma unroll
            for (int i = 0; i < 32; i++) {
                ulonglong2 hv = h2[i];
                a0 = f2fma(w[2 * i],     hv.x, a0);
                a1 = f2fma(w[2 * i + 1], hv.y, a1);
            }
            float l0, h0, l1, h1; upk(a0, l0, h0); upk(a1, l1, h1);
            pxB[u] = (l0 + h0) + (l1 + h1) + bh;

            if (u < 128) {
                const float r = fsig(frA + pxA[u]);
                const float z = fsig(fzA + pxA[u + 128]);
                const float n = ftanh_f(fnA + r * pxA[u + 256]);
                const float hnew = (1.f - z) * n + z * hA[u];
                hA[u] = hnew;
                opA[(size_t)t * Hh + u] = hnew;
                const float* nx = gxA + (size_t)tn * 384;
                frA = __ldg(nx + u); fzA = __ldg(nx + u + 128); fnA = __ldg(nx + u + 256);
            }
        }
        __syncthreads();
    }
}

// ============================================================
// Kernel E: temporal LayerNorm, in-place. One warp per row.
// ============================================================
__global__ __launch_bounds__(256) void tln_kernel(float* __restrict__ out,
                                                  const float* __restrict__ g,
                                                  const float* __restrict__ b)
{
    const int warp = threadIdx.x >> 5, lane = threadIdx.x & 31;
    const size_t row = (size_t)blockIdx.x * 8 + warp;
    float4* p = (float4*)(out + row * Hh);
    float4 v = p[lane];
    float s = v.x + v.y + v.z + v.w;
    float q = v.x * v.x + v.y * v.y + v.z * v.z + v.w * v.w;
#pragma unroll
    for (int off = 16; off; off >>= 1) {
        s += __shfl_xor_sync(0xffffffffu, s, off);
        q += __shfl_xor_sync(0xffffffffu, q, off);
    }
    const float mean = s * (1.f / Hh);
    const float var  = q * (1.f / Hh) - mean * mean;
    const float rstd = rsqrtf(var + 1e-5f);
    const float4 gv = ((const float4*)g)[lane];
    const float4 bv = ((const float4*)b)[lane];
    v.x = (v.x - mean) * rstd * gv.x + bv.x;
    v.y = (v.y - mean) * rstd * gv.y + bv.y;
    v.z = (v.z - mean) * rstd * gv.z + bv.z;
    v.w = (v.w - mean) * rstd * gv.w + bv.w;
    p[lane] = v;
}

// ============================================================
extern "C" void kernel_launch(void* const* d_in, const int* in_sizes, int n_in,
                              void* d_out, int out_size)
{
    const float* x      = (const float*)d_in[0];
    const float* gat_W  = (const float*)d_in[1];
    const float* gat_b  = (const float*)d_in[2];
    const float* a_src  = (const float*)d_in[3];
    const float* a_dst  = (const float*)d_in[4];
    const float* abias  = (const float*)d_in[5];
    const float* sn_g   = (const float*)d_in[6];
    const float* sn_b   = (const float*)d_in[7];
    const float* W_ih   = (const float*)d_in[8];
    const float* W_hh   = (const float*)d_in[9];
    const float* b_ih   = (const float*)d_in[10];
    const float* b_hh   = (const float*)d_in[11];
    const float* tn_g   = (const float*)d_in[12];
    const float* tn_b   = (const float*)d_in[13];
    float* out = (float*)d_out;

    gat_kernel<<<ROWS / 16, 128>>>(x, gat_W, gat_b);
    attn_kernel<<<(Bb * Tt) / 8, 256>>>(a_src, a_dst, abias, sn_g, sn_b);
    gx_kernel<<<dim3(ROWS / 32, 3), 256>>>(W_ih, b_ih);
    gru_kernel<<<Bb * Nn / 2, 384>>>(W_hh, b_hh, out);
    tln_kernel<<<ROWS / 8, 256>>>(out, tn_g, tn_b);
}